// round 2
// baseline (speedup 1.0000x reference)
#include <cuda_runtime.h>
#include <cstdint>

#define BATCH 16
#define A_N   261888
#define PRE   2000
#define POST  1000
#define NB    256           // histogram buckets over [0,1)
#define CAP   4096          // candidate capacity per image (sort size, power of 2)
#define NW    32            // 32 x uint64 words cover 2048 >= PRE bits
#define IMGF      1024.0f
#define NMS_THR_F 0.7f
#define MIN_SZ_F  16.0f

// ---------------- device scratch (static: no allocation allowed) ----------------
__device__ float               g_score[BATCH * A_N];        // masked score, -1 = invalid
__device__ int                 g_hist[BATCH * NB];
__device__ int                 g_cnt[BATCH];
__device__ unsigned long long  g_cand[BATCH * CAP];
__device__ float4              g_box[BATCH * PRE];
__device__ float               g_sc2[BATCH * PRE];
__device__ unsigned long long  g_mask[BATCH * PRE * NW];    // 8.2 MB IoU suppression bits

// ---------------- fast exp: no MUFU, ~5e-9 rel err (Cody-Waite + deg-7 poly) ----
__device__ __forceinline__ float fast_exp(float x) {
    x = fmaxf(x, -80.0f);                       // exp(-80) => width 0 => invalid either way
    const float L2E = 1.4426950408889634f;
    const float LN2_HI = 0.693145751953125f;
    const float LN2_LO = 1.42860677e-6f;
    float z = fmaf(x, L2E, 12582912.0f);        // round-to-nearest via magic number
    float nf = z - 12582912.0f;
    int   ni = __float_as_int(z) - 0x4B400000;
    float t = fmaf(nf, -LN2_HI, x);
    t = fmaf(nf, -LN2_LO, t);
    // e^t, t in [-0.347, 0.347], Taylor deg 7
    float p = 1.9841270e-4f;
    p = fmaf(p, t, 1.3888889e-3f);
    p = fmaf(p, t, 8.3333338e-3f);
    p = fmaf(p, t, 4.1666668e-2f);
    p = fmaf(p, t, 1.6666667e-1f);
    p = fmaf(p, t, 5.0e-1f);
    p = fmaf(p, t, 1.0f);
    p = fmaf(p, t, 1.0f);
    return p * __int_as_float((ni + 127) << 23);
}

// ---------------- decode + clip, matching reference order of ops ----------------
__device__ __forceinline__ float4 decode_clip(const float4 a, const float4 d) {
    float aw = a.z - a.x;
    float ah = a.w - a.y;
    float ax = a.x + 0.5f * aw;
    float ay = a.y + 0.5f * ah;
    float dw = fminf(d.z, 4.0f);
    float dh = fminf(d.w, 4.0f);
    float px = d.x * aw + ax;
    float py = d.y * ah + ay;
    float pw = fast_exp(dw) * aw;
    float ph = fast_exp(dh) * ah;
    float x1 = fminf(fmaxf(px - 0.5f * pw, 0.0f), IMGF);
    float y1 = fminf(fmaxf(py - 0.5f * ph, 0.0f), IMGF);
    float x2 = fminf(fmaxf(px + 0.5f * pw, 0.0f), IMGF);
    float y2 = fminf(fmaxf(py + 0.5f * ph, 0.0f), IMGF);
    return make_float4(x1, y1, x2, y2);
}

// ---------------- kernel 0: zero per-launch state ----------------
__global__ void k_zero() {
    int i = blockIdx.x * blockDim.x + threadIdx.x;
    if (i < BATCH * NB) g_hist[i] = 0;
    if (i < BATCH) g_cnt[i] = 0;
}

// ---------------- kernel 1: decode, mask, histogram ----------------
__global__ void k_decode(const float4* __restrict__ anchors,
                         const float4* __restrict__ deltas,
                         const float* __restrict__ scores) {
    __shared__ int h[NB];
    int b = blockIdx.x >> 6;
    int chunk = blockIdx.x & 63;
    const int per = A_N / 64;          // 4092 exactly
    int start = chunk * per;
    if (threadIdx.x < NB) h[threadIdx.x] = 0;
    __syncthreads();
    for (int i = start + threadIdx.x; i < start + per; i += blockDim.x) {
        float4 a = anchors[i];
        float4 d = deltas[(size_t)b * A_N + i];
        float  s = scores[(size_t)b * A_N + i];
        float4 bx = decode_clip(a, d);
        bool valid = (bx.z - bx.x >= MIN_SZ_F) && (bx.w - bx.y >= MIN_SZ_F);
        g_score[(size_t)b * A_N + i] = valid ? s : -1.0f;
        if (valid) {
            int bk = min(max((int)(s * (float)NB), 0), NB - 1);
            atomicAdd(&h[bk], 1);
        }
    }
    __syncthreads();
    if (threadIdx.x < NB) {
        int v = h[threadIdx.x];
        if (v) atomicAdd(&g_hist[b * NB + threadIdx.x], v);
    }
}

// ---------------- kernel 2: threshold (inline) + block-aggregated collect ------
__global__ void k_collect() {
    __shared__ int sh[NB];
    __shared__ int s_thr, s_cnt, s_base;
    int b = blockIdx.x >> 6;
    int chunk = blockIdx.x & 63;
    const int per = A_N / 64;
    int start = chunk * per;
    int tid = threadIdx.x;
    if (tid < NB) sh[tid] = g_hist[b * NB + tid];
    if (tid == 0) s_cnt = 0;
    __syncthreads();
    if (tid == 0) {
        int run = 0, thr = 0;
        #pragma unroll 8
        for (int k = NB - 1; k >= 0; k--) {
            run += sh[k];
            if (run >= PRE) { thr = k; break; }
        }
        s_thr = thr;
    }
    __syncthreads();
    float thrf = (float)s_thr;
    // gather local candidates into registers
    int   li[8];
    float lv[8];
    int c = 0;
    for (int i = start + tid; i < start + per; i += blockDim.x) {
        float s = g_score[(size_t)b * A_N + i];
        if (s >= 0.0f) {
            float bkf = fminf(floorf(s * (float)NB), (float)(NB - 1));
            if (bkf >= thrf) { li[c] = i; lv[c] = s; c++; }
        }
    }
    int ofs = 0;
    if (c) ofs = atomicAdd(&s_cnt, c);
    __syncthreads();
    if (tid == 0) s_base = s_cnt ? atomicAdd(&g_cnt[b], s_cnt) : 0;
    __syncthreads();
    int base = s_base + ofs;
    for (int k = 0; k < c; k++) {
        int pos = base + k;
        if (pos < CAP) {
            unsigned lo = ~(unsigned)li[k];   // lower index wins ties
            g_cand[b * CAP + pos] =
                ((unsigned long long)__float_as_uint(lv[k]) << 32) | lo;
        }
    }
}

// ---------------- kernel 3: bitonic sort (desc) + gather top-PRE boxes ----------
__global__ void k_sort(const float4* __restrict__ anchors,
                       const float4* __restrict__ deltas) {
    __shared__ unsigned long long sk[CAP];   // 32 KB
    int b = blockIdx.x;
    int C = min(g_cnt[b], CAP);
    for (int i = threadIdx.x; i < CAP; i += blockDim.x)
        sk[i] = (i < C) ? g_cand[b * CAP + i] : 0ull;
    __syncthreads();
    for (int k = 2; k <= CAP; k <<= 1) {
        for (int j = k >> 1; j > 0; j >>= 1) {
            for (int i = threadIdx.x; i < CAP; i += blockDim.x) {
                int ixj = i ^ j;
                if (ixj > i) {
                    bool up = (i & k) == 0;   // up segment -> descending order
                    unsigned long long x = sk[i], y = sk[ixj];
                    bool sw = up ? (x < y) : (x > y);
                    if (sw) { sk[i] = y; sk[ixj] = x; }
                }
            }
            __syncthreads();
        }
    }
    for (int i = threadIdx.x; i < PRE; i += blockDim.x) {
        unsigned long long key = sk[i];
        unsigned idx = ~(unsigned)(key & 0xffffffffu);
        float sc;
        float4 bx;
        if (key != 0ull && idx < A_N) {
            sc = __uint_as_float((unsigned)(key >> 32));
            bx = decode_clip(anchors[idx], deltas[(size_t)b * A_N + idx]);
        } else {
            sc = 0.0f;
            bx = make_float4(0.f, 0.f, 0.f, 0.f);
        }
        g_box[b * PRE + i] = bx;
        g_sc2[b * PRE + i] = sc;
    }
}

// ---------------- kernel 4: IoU suppression bitmask ----------------
__global__ void k_iou() {
    __shared__ float4 cb[64];
    __shared__ float  ca[64];
    int b = blockIdx.z;
    int rowbase = blockIdx.y * 64;
    int colbase = blockIdx.x * 64;
    int t = threadIdx.x;
    int j = colbase + t;
    float4 cj = (j < PRE) ? g_box[b * PRE + j] : make_float4(0.f, 0.f, 0.f, 0.f);
    cb[t] = cj;
    ca[t] = (cj.z - cj.x) * (cj.w - cj.y);
    __syncthreads();
    int i = rowbase + t;
    if (i >= PRE) return;
    float4 bi = g_box[b * PRE + i];
    float  ai = (bi.z - bi.x) * (bi.w - bi.y);
    unsigned long long word = 0ull;
    if (colbase + 63 > i) {
        #pragma unroll 8
        for (int jj = 0; jj < 64; jj++) {
            int jg = colbase + jj;
            if (jg > i && jg < PRE) {
                float4 bb = cb[jj];
                float lx = fmaxf(bi.x, bb.x), ly = fmaxf(bi.y, bb.y);
                float rx = fminf(bi.z, bb.z), ry = fminf(bi.w, bb.w);
                float w = fmaxf(rx - lx, 0.0f), h = fmaxf(ry - ly, 0.0f);
                float inter = w * h;
                float iou = inter / (ai + ca[jj] - inter + 1e-6f);
                if (iou > NMS_THR_F) word |= (1ull << jj);
            }
        }
    }
    g_mask[((size_t)b * PRE + i) * NW + blockIdx.x] = word;
}

// ---------------- kernel 5: greedy scan (1 warp / image) + fused output --------
__global__ void k_nms_out(float* __restrict__ out) {
    __shared__ unsigned long long sdec[2][64];   // decision-word double buffer
    const int NCH = (PRE + 63) / 64;             // 32 (last chunk: 16 rows)
    int b = blockIdx.x;
    int lane = threadIdx.x;                      // blockDim = 32
    const unsigned long long* __restrict__ M = &g_mask[(size_t)b * PRE * NW];
    const unsigned FULL = 0xffffffffu;

    // preload decision words for chunk 0 (rows r, word 0)
    for (int k = lane; k < 64; k += 32)
        sdec[0][k] = M[(size_t)k * NW + 0];
    __syncwarp();

    unsigned long long remv = 0ull;              // lane t owns removal word t
    for (int c = 0; c < NCH; c++) {
        unsigned long long cur = __shfl_sync(FULL, remv, c);
        unsigned keptlo = 0, kepthi = 0;
        unsigned long long newcur = 0ull;
        if (lane == 0) {
            unsigned clo = (unsigned)cur, chi = (unsigned)(cur >> 32);
            const unsigned long long* dp = sdec[c & 1];
            #pragma unroll
            for (int r = 0; r < 32; r++) {
                unsigned long long d = dp[r];
                unsigned sel = ((clo >> r) & 1u) - 1u;     // kept -> ~0, suppressed -> 0
                clo |= (unsigned)d & sel;
                chi |= (unsigned)(d >> 32) & sel;
            }
            #pragma unroll
            for (int r = 32; r < 64; r++) {
                unsigned long long d = dp[r];
                unsigned sel = ((chi >> (r - 32)) & 1u) - 1u;
                chi |= (unsigned)(d >> 32) & sel;          // low half of d is 0 here
            }
            keptlo = ~clo; kepthi = ~chi;
            newcur = ((unsigned long long)chi << 32) | clo;
        }
        unsigned klo = __shfl_sync(FULL, keptlo, 0);
        unsigned khi = __shfl_sync(FULL, kepthi, 0);
        newcur = __shfl_sync(FULL, newcur, 0);
        if (lane == c) remv = newcur;
        if (c == NCH - 1) { klo &= 0xFFFFu; khi = 0u; }    // only 16 valid rows in last chunk

        // prefetch next chunk's decision words
        if (c + 1 < NCH) {
            int nb2 = (c + 1) * 64;
            for (int k = lane; k < 64; k += 32) {
                int row = nb2 + k;
                sdec[(c + 1) & 1][k] = (row < PRE) ? M[(size_t)row * NW + (c + 1)] : 0ull;
            }
        }
        // accumulate suppression from kept rows into all words (parallel over lanes)
        int base = c * 64;
        #pragma unroll 4
        for (int r = 0; r < 32; r++)
            if ((klo >> r) & 1u) remv |= M[(size_t)(base + r) * NW + lane];
        #pragma unroll 4
        for (int r = 0; r < 32; r++)
            if ((khi >> r) & 1u) remv |= M[(size_t)(base + 32 + r) * NW + lane];
        __syncwarp();
    }

    // output: compact kept boxes (score-desc order = index order)
    unsigned long long keepw = ~remv;
    if (lane == NW - 1) keepw &= (1ull << (PRE - (NW - 1) * 64)) - 1ull;  // 16 bits
    int pc = __popcll(keepw);
    int inc = pc;
    #pragma unroll
    for (int o = 1; o < 32; o <<= 1) {
        int n = __shfl_up_sync(FULL, inc, o);
        if (lane >= o) inc += n;
    }
    int pref = inc - pc;   // exclusive prefix of kept counts

    float* ob = &out[(size_t)b * POST * 5];
    for (int i = lane; i < POST * 5; i += 32) ob[i] = 0.0f;
    __syncwarp();

    unsigned long long w = keepw;
    int r = pref;
    while (w) {
        int bit = __ffsll((long long)w) - 1;
        w &= w - 1;
        if (r < POST) {
            int i = lane * 64 + bit;
            float4 bx = g_box[b * PRE + i];
            float sc = g_sc2[b * PRE + i];
            float* o = &ob[(size_t)r * 5];
            o[0] = bx.x; o[1] = bx.y; o[2] = bx.z; o[3] = bx.w; o[4] = sc;
        }
        r++;
    }
}

// ---------------- launch ----------------
extern "C" void kernel_launch(void* const* d_in, const int* in_sizes, int n_in,
                              void* d_out, int out_size) {
    const float4* anchors = (const float4*)d_in[0];   // (A,4)
    const float4* deltas  = (const float4*)d_in[1];   // (B,A,4)
    const float*  scores  = (const float*)d_in[2];    // (B,A)
    float* out = (float*)d_out;                        // (B,POST,5)

    k_zero    <<<4, 1024>>>();
    k_decode  <<<BATCH * 64, 512>>>(anchors, deltas, scores);
    k_collect <<<BATCH * 64, 512>>>();
    k_sort    <<<BATCH, 1024>>>(anchors, deltas);
    k_iou     <<<dim3(NW, (PRE + 63) / 64, BATCH), 64>>>();
    k_nms_out <<<BATCH, 32>>>(out);
}

// round 4
// speedup vs baseline: 1.5334x; 1.5334x over previous
#include <cuda_runtime.h>
#include <cstdint>

#define BATCH 16
#define A_N   261888
#define PRE   2000
#define POST  1000
#define NB    256           // histogram buckets over [0,1)
#define CAP   4096          // candidate capacity per image (sort size, power of 2)
#define NW    32            // 32 x uint64 words cover 2048 >= PRE bits
#define IMGF      1024.0f
#define NMS_THR_F 0.7f
#define MIN_SZ_F  16.0f

typedef unsigned long long u64;

// ---------------- device scratch (static: no allocation allowed) ----------------
__device__ float  g_score[BATCH * A_N];        // masked score, -1 = invalid
__device__ int    g_hist[BATCH * NB];
__device__ int    g_cnt[BATCH];
__device__ u64    g_cand[BATCH * CAP];
__device__ float4 g_box[BATCH * PRE];
__device__ float  g_sc2[BATCH * PRE];
__device__ u64    g_mask[BATCH * PRE * NW];    // 8.2 MB IoU bits (lower tri stays 0)

// ---------------- fast exp: no MUFU, ~5e-9 rel err ----------------
__device__ __forceinline__ float fast_exp(float x) {
    x = fmaxf(x, -80.0f);
    const float L2E = 1.4426950408889634f;
    const float LN2_HI = 0.693145751953125f;
    const float LN2_LO = 1.42860677e-6f;
    float z = fmaf(x, L2E, 12582912.0f);
    float nf = z - 12582912.0f;
    int   ni = __float_as_int(z) - 0x4B400000;
    float t = fmaf(nf, -LN2_HI, x);
    t = fmaf(nf, -LN2_LO, t);
    float p = 1.9841270e-4f;
    p = fmaf(p, t, 1.3888889e-3f);
    p = fmaf(p, t, 8.3333338e-3f);
    p = fmaf(p, t, 4.1666668e-2f);
    p = fmaf(p, t, 1.6666667e-1f);
    p = fmaf(p, t, 5.0e-1f);
    p = fmaf(p, t, 1.0f);
    p = fmaf(p, t, 1.0f);
    return p * __int_as_float((ni + 127) << 23);
}

__device__ __forceinline__ float4 decode_clip(const float4 a, const float4 d) {
    float aw = a.z - a.x;
    float ah = a.w - a.y;
    float ax = a.x + 0.5f * aw;
    float ay = a.y + 0.5f * ah;
    float dw = fminf(d.z, 4.0f);
    float dh = fminf(d.w, 4.0f);
    float px = d.x * aw + ax;
    float py = d.y * ah + ay;
    float pw = fast_exp(dw) * aw;
    float ph = fast_exp(dh) * ah;
    float x1 = fminf(fmaxf(px - 0.5f * pw, 0.0f), IMGF);
    float y1 = fminf(fmaxf(py - 0.5f * ph, 0.0f), IMGF);
    float x2 = fminf(fmaxf(px + 0.5f * pw, 0.0f), IMGF);
    float y2 = fminf(fmaxf(py + 0.5f * ph, 0.0f), IMGF);
    return make_float4(x1, y1, x2, y2);
}

// ---------------- kernel 0: zero per-launch state ----------------
__global__ void k_zero() {
    int i = blockIdx.x * blockDim.x + threadIdx.x;
    if (i < BATCH * NB) g_hist[i] = 0;
    if (i < BATCH) g_cnt[i] = 0;
}

// ---------------- kernel 1: decode, mask, histogram ----------------
__global__ void k_decode(const float4* __restrict__ anchors,
                         const float4* __restrict__ deltas,
                         const float* __restrict__ scores) {
    __shared__ int h[NB];
    int b = blockIdx.x >> 6;
    int chunk = blockIdx.x & 63;
    const int per = A_N / 64;          // 4092 exactly
    int start = chunk * per;
    if (threadIdx.x < NB) h[threadIdx.x] = 0;
    __syncthreads();
    for (int i = start + threadIdx.x; i < start + per; i += blockDim.x) {
        float4 a = anchors[i];
        float4 d = deltas[(size_t)b * A_N + i];
        float  s = scores[(size_t)b * A_N + i];
        float4 bx = decode_clip(a, d);
        bool valid = (bx.z - bx.x >= MIN_SZ_F) && (bx.w - bx.y >= MIN_SZ_F);
        g_score[(size_t)b * A_N + i] = valid ? s : -1.0f;
        if (valid) {
            int bk = min(max((int)(s * (float)NB), 0), NB - 1);
            atomicAdd(&h[bk], 1);
        }
    }
    __syncthreads();
    if (threadIdx.x < NB) {
        int v = h[threadIdx.x];
        if (v) atomicAdd(&g_hist[b * NB + threadIdx.x], v);
    }
}

// ---------------- kernel 2: threshold (inline) + block-aggregated collect ------
__global__ void k_collect() {
    __shared__ int sh[NB];
    __shared__ int s_thr, s_cnt, s_base;
    int b = blockIdx.x >> 6;
    int chunk = blockIdx.x & 63;
    const int per = A_N / 64;
    int start = chunk * per;
    int tid = threadIdx.x;
    if (tid < NB) sh[tid] = g_hist[b * NB + tid];
    if (tid == 0) s_cnt = 0;
    __syncthreads();
    if (tid == 0) {
        int run = 0, thr = 0;
        #pragma unroll 8
        for (int k = NB - 1; k >= 0; k--) {
            run += sh[k];
            if (run >= PRE) { thr = k; break; }
        }
        s_thr = thr;
    }
    __syncthreads();
    float thrf = (float)s_thr;
    int   li[8];
    float lv[8];
    int c = 0;
    for (int i = start + tid; i < start + per; i += blockDim.x) {
        float s = g_score[(size_t)b * A_N + i];
        if (s >= 0.0f) {
            float bkf = fminf(floorf(s * (float)NB), (float)(NB - 1));
            if (bkf >= thrf) { li[c] = i; lv[c] = s; c++; }
        }
    }
    int ofs = 0;
    if (c) ofs = atomicAdd(&s_cnt, c);
    __syncthreads();
    if (tid == 0) s_base = s_cnt ? atomicAdd(&g_cnt[b], s_cnt) : 0;
    __syncthreads();
    int base = s_base + ofs;
    for (int k = 0; k < c; k++) {
        int pos = base + k;
        if (pos < CAP) {
            unsigned lo = ~(unsigned)li[k];   // lower index wins ties
            g_cand[b * CAP + pos] = ((u64)__float_as_uint(lv[k]) << 32) | lo;
        }
    }
}

// ---------------- kernel 3: register bitonic sort (desc) + gather ----------------
__device__ __forceinline__ void cex(u64& a, u64& b, bool desc) {
    bool sw = desc ? (a < b) : (a > b);
    if (sw) { u64 t = a; a = b; b = t; }
}

__global__ void k_sort(const float4* __restrict__ anchors,
                       const float4* __restrict__ deltas) {
    __shared__ u64 sh[CAP];                  // 32 KB, used only for j>=128 steps
    const unsigned FULL = 0xffffffffu;
    int b = blockIdx.x;
    int t = threadIdx.x;                     // 1024 threads, thread owns g=4t..4t+3
    int C = min(g_cnt[b], CAP);
    u64 v[4];
    #pragma unroll
    for (int m = 0; m < 4; m++) {
        int g = t * 4 + m;
        v[m] = (g < C) ? g_cand[b * CAP + g] : 0ull;
    }
    int g0 = t * 4;
    for (int k = 2; k <= CAP; k <<= 1) {
        for (int j = k >> 1; j > 0; j >>= 1) {
            if (j >= 128) {
                #pragma unroll
                for (int m = 0; m < 4; m++) sh[g0 + m] = v[m];
                __syncthreads();
                bool lower = (g0 & j) == 0;
                bool desc  = (g0 & k) == 0;
                bool kmax  = (desc == lower);
                #pragma unroll
                for (int m = 0; m < 4; m++) {
                    u64 pv = sh[(g0 + m) ^ j];
                    u64 a = v[m];
                    bool takep = kmax ? (pv > a) : (pv < a);
                    v[m] = takep ? pv : a;
                }
                __syncthreads();
            } else if (j >= 4) {
                int lm = j >> 2;
                bool lower = (g0 & j) == 0;
                bool desc  = (g0 & k) == 0;
                bool kmax  = (desc == lower);
                #pragma unroll
                for (int m = 0; m < 4; m++) {
                    u64 pv = __shfl_xor_sync(FULL, v[m], lm);
                    u64 a = v[m];
                    bool takep = kmax ? (pv > a) : (pv < a);
                    v[m] = takep ? pv : a;
                }
            } else if (j == 2) {
                bool desc = (g0 & k) == 0;
                cex(v[0], v[2], desc);
                cex(v[1], v[3], desc);
            } else { // j == 1
                if (k == 2) {
                    cex(v[0], v[1], true);
                    cex(v[2], v[3], false);
                } else {
                    bool desc = (g0 & k) == 0;
                    cex(v[0], v[1], desc);
                    cex(v[2], v[3], desc);
                }
            }
        }
    }
    // gather top-PRE
    #pragma unroll
    for (int m = 0; m < 4; m++) {
        int g = g0 + m;
        if (g < PRE) {
            u64 key = v[m];
            unsigned idx = ~(unsigned)(key & 0xffffffffu);
            float sc;
            float4 bx;
            if (key != 0ull && idx < A_N) {
                sc = __uint_as_float((unsigned)(key >> 32));
                bx = decode_clip(anchors[idx], deltas[(size_t)b * A_N + idx]);
            } else {
                sc = 0.0f;
                bx = make_float4(0.f, 0.f, 0.f, 0.f);
            }
            g_box[b * PRE + g] = bx;
            g_sc2[b * PRE + g] = sc;
        }
    }
}

// ---------------- kernel 4: IoU suppression bitmask (upper triangle only) -------
__global__ void k_iou() {
    __shared__ float4 cb[64];
    __shared__ float  ca[64];
    int rowbase = blockIdx.y * 64;
    int colbase = blockIdx.x * 64;
    if (colbase + 63 <= rowbase) return;     // lower-tri words stay 0 (zero-init)
    int b = blockIdx.z;
    int t = threadIdx.x;
    int j = colbase + t;
    float4 cj = (j < PRE) ? g_box[b * PRE + j] : make_float4(0.f, 0.f, 0.f, 0.f);
    cb[t] = cj;
    ca[t] = (cj.z - cj.x) * (cj.w - cj.y);
    __syncthreads();
    int i = rowbase + t;
    if (i >= PRE) return;
    float4 bi = g_box[b * PRE + i];
    float  ai = (bi.z - bi.x) * (bi.w - bi.y);
    u64 word = 0ull;
    #pragma unroll 8
    for (int jj = 0; jj < 64; jj++) {
        int jg = colbase + jj;
        if (jg > i && jg < PRE) {
            float4 bb = cb[jj];
            float lx = fmaxf(bi.x, bb.x), ly = fmaxf(bi.y, bb.y);
            float rx = fminf(bi.z, bb.z), ry = fminf(bi.w, bb.w);
            float w = fmaxf(rx - lx, 0.0f), h = fmaxf(ry - ly, 0.0f);
            float inter = w * h;
            float iou = inter / (ai + ca[jj] - inter + 1e-6f);
            if (iou > NMS_THR_F) word |= (1ull << jj);
        }
    }
    g_mask[((size_t)b * PRE + i) * NW + blockIdx.x] = word;
}

// ---------------- kernel 5: greedy scan + fused output -------------------------
// 1024 threads: warp 0 = serial scan (all operands in shared/registers),
// warps 1..31 = double-buffer prefetch of full 64-row x 32-word mask chunks.
__global__ void k_nms_out(float* __restrict__ out) {
    __shared__ u64 buf[2][64 * NW];          // 32 KB double buffer
    const int NCH = (PRE + 63) / 64;         // 32 (last chunk: 16 rows)
    const unsigned FULL = 0xffffffffu;
    int b = blockIdx.x;
    int tid = threadIdx.x;
    int warp = tid >> 5;
    int lane = tid & 31;
    const u64* __restrict__ M = &g_mask[(size_t)b * PRE * NW];

    // preload chunk 0
    for (int i = tid; i < 64 * NW; i += 1024) buf[0][i] = M[i];
    __syncthreads();

    u64 remv = 0ull;                         // warp0: lane t owns removal word t
    for (int c = 0; c < NCH; c++) {
        if (warp == 0) {
            const u64* dp = buf[c & 1];
            u64 cur = __shfl_sync(FULL, remv, c);
            unsigned keptlo = 0, kepthi = 0;
            u64 newcur = 0ull;
            if (lane == 0) {
                unsigned clo = (unsigned)cur, chi = (unsigned)(cur >> 32);
                #pragma unroll
                for (int r = 0; r < 32; r++) {
                    u64 d = dp[r * NW + c];
                    unsigned sel = ((clo >> r) & 1u) - 1u;   // kept -> ~0
                    clo |= (unsigned)d & sel;
                    chi |= (unsigned)(d >> 32) & sel;
                }
                #pragma unroll
                for (int r = 32; r < 64; r++) {
                    u64 d = dp[r * NW + c];
                    unsigned sel = ((chi >> (r - 32)) & 1u) - 1u;
                    chi |= (unsigned)(d >> 32) & sel;        // low half is 0 here
                }
                keptlo = ~clo; kepthi = ~chi;
                newcur = ((u64)chi << 32) | clo;
            }
            unsigned klo = __shfl_sync(FULL, keptlo, 0);
            unsigned khi = __shfl_sync(FULL, kepthi, 0);
            newcur = __shfl_sync(FULL, newcur, 0);
            if (c == NCH - 1) { klo &= 0xFFFFu; khi = 0u; }  // 16 valid rows
            if (lane == c) remv = newcur;
            // OR kept rows' full mask rows from SHARED into remv (parallel lanes)
            #pragma unroll 4
            for (int r = 0; r < 32; r++)
                if ((klo >> r) & 1u) remv |= dp[r * NW + lane];
            #pragma unroll 4
            for (int r = 0; r < 32; r++)
                if ((khi >> r) & 1u) remv |= dp[(r + 32) * NW + lane];
        } else if (c + 1 < NCH) {
            // prefetch chunk c+1
            int base = (c + 1) * 64;
            for (int i = tid - 32; i < 64 * NW; i += 992) {
                int r = i >> 5, w = i & 31;
                int row = base + r;
                buf[(c + 1) & 1][i] = (row < PRE) ? M[(size_t)row * NW + w] : 0ull;
            }
        }
        __syncthreads();
    }

    // zero output
    float* ob = &out[(size_t)b * POST * 5];
    for (int i = tid; i < POST * 5; i += 1024) ob[i] = 0.0f;
    __syncthreads();

    if (warp == 0) {
        u64 keepw = ~remv;
        if (lane == NW - 1) keepw &= (1ull << (PRE - (NW - 1) * 64)) - 1ull;
        int pc = __popcll(keepw);
        int inc = pc;
        #pragma unroll
        for (int o = 1; o < 32; o <<= 1) {
            int n = __shfl_up_sync(FULL, inc, o);
            if (lane >= o) inc += n;
        }
        int r = inc - pc;                    // exclusive prefix
        u64 w = keepw;
        while (w) {
            int bit = __ffsll((long long)w) - 1;
            w &= w - 1;
            if (r < POST) {
                int i = lane * 64 + bit;
                float4 bx = g_box[b * PRE + i];
                float sc = g_sc2[b * PRE + i];
                float* o = &ob[(size_t)r * 5];
                o[0] = bx.x; o[1] = bx.y; o[2] = bx.z; o[3] = bx.w; o[4] = sc;
            }
            r++;
        }
    }
}

// ---------------- launch ----------------
extern "C" void kernel_launch(void* const* d_in, const int* in_sizes, int n_in,
                              void* d_out, int out_size) {
    const float4* anchors = (const float4*)d_in[0];   // (A,4)
    const float4* deltas  = (const float4*)d_in[1];   // (B,A,4)
    const float*  scores  = (const float*)d_in[2];    // (B,A)
    float* out = (float*)d_out;                        // (B,POST,5)

    k_zero    <<<4, 1024>>>();
    k_decode  <<<BATCH * 64, 512>>>(anchors, deltas, scores);
    k_collect <<<BATCH * 64, 512>>>();
    k_sort    <<<BATCH, 1024>>>(anchors, deltas);
    k_iou     <<<dim3(NW, (PRE + 63) / 64, BATCH), 64>>>();
    k_nms_out <<<BATCH, 1024>>>(out);
}

// round 5
// speedup vs baseline: 1.5988x; 1.0426x over previous
#include <cuda_runtime.h>
#include <cstdint>

#define BATCH 16
#define A_N   261888
#define PRE   2000
#define POST  1000
#define NB    8192          // histogram buckets over [0,1)
#define CAP   4096          // candidate storage (sort 2048 fast path, 4096 fallback)
#define NW    32            // 32 x uint64 words cover 2048 >= PRE bits
#define IMGF      1024.0f
#define NMS_THR_F 0.7f
#define MIN_SZ_F  16.0f

typedef unsigned long long u64;

// ---------------- device scratch (static: no allocation allowed) ----------------
__device__ float  g_score[BATCH * A_N];        // masked score, -1 = invalid
__device__ int    g_hist[BATCH * NB];
__device__ int    g_thr[BATCH];
__device__ int    g_cnt[BATCH];
__device__ u64    g_cand[BATCH * CAP];
__device__ float4 g_box[BATCH * PRE];
__device__ float  g_sc2[BATCH * PRE];
__device__ u64    g_mask[BATCH * PRE * NW];    // 8.2 MB IoU bits (lower tri stays 0)

// ---------------- fast exp: no MUFU, ~5e-9 rel err ----------------
__device__ __forceinline__ float fast_exp(float x) {
    x = fmaxf(x, -80.0f);
    const float L2E = 1.4426950408889634f;
    const float LN2_HI = 0.693145751953125f;
    const float LN2_LO = 1.42860677e-6f;
    float z = fmaf(x, L2E, 12582912.0f);
    float nf = z - 12582912.0f;
    int   ni = __float_as_int(z) - 0x4B400000;
    float t = fmaf(nf, -LN2_HI, x);
    t = fmaf(nf, -LN2_LO, t);
    float p = 1.9841270e-4f;
    p = fmaf(p, t, 1.3888889e-3f);
    p = fmaf(p, t, 8.3333338e-3f);
    p = fmaf(p, t, 4.1666668e-2f);
    p = fmaf(p, t, 1.6666667e-1f);
    p = fmaf(p, t, 5.0e-1f);
    p = fmaf(p, t, 1.0f);
    p = fmaf(p, t, 1.0f);
    return p * __int_as_float((ni + 127) << 23);
}

__device__ __forceinline__ float4 decode_clip(const float4 a, const float4 d) {
    float aw = a.z - a.x;
    float ah = a.w - a.y;
    float ax = a.x + 0.5f * aw;
    float ay = a.y + 0.5f * ah;
    float dw = fminf(d.z, 4.0f);
    float dh = fminf(d.w, 4.0f);
    float px = d.x * aw + ax;
    float py = d.y * ah + ay;
    float pw = fast_exp(dw) * aw;
    float ph = fast_exp(dh) * ah;
    float x1 = fminf(fmaxf(px - 0.5f * pw, 0.0f), IMGF);
    float y1 = fminf(fmaxf(py - 0.5f * ph, 0.0f), IMGF);
    float x2 = fminf(fmaxf(px + 0.5f * pw, 0.0f), IMGF);
    float y2 = fminf(fmaxf(py + 0.5f * ph, 0.0f), IMGF);
    return make_float4(x1, y1, x2, y2);
}

__device__ __forceinline__ int bucket_of(float s) {
    int bk = (int)(s * (float)NB);
    return bk > NB - 1 ? NB - 1 : bk;
}

// ---------------- kernel 0: zero per-launch state ----------------
__global__ void k_zero() {
    int i = blockIdx.x * blockDim.x + threadIdx.x;
    if (i < BATCH * NB) g_hist[i] = 0;
    if (i < BATCH) g_cnt[i] = 0;
}

// ---------------- kernel 1: decode, mask, fine histogram ----------------
__global__ void k_decode(const float4* __restrict__ anchors,
                         const float4* __restrict__ deltas,
                         const float* __restrict__ scores) {
    __shared__ int h[NB];                  // 32 KB
    int b = blockIdx.x >> 6;
    int chunk = blockIdx.x & 63;
    const int per = A_N / 64;              // 4092 exactly
    int start = chunk * per;
    for (int i = threadIdx.x; i < NB; i += blockDim.x) h[i] = 0;
    __syncthreads();
    for (int i = start + threadIdx.x; i < start + per; i += blockDim.x) {
        float4 a = anchors[i];
        float4 d = deltas[(size_t)b * A_N + i];
        float  s = scores[(size_t)b * A_N + i];
        float4 bx = decode_clip(a, d);
        bool valid = (bx.z - bx.x >= MIN_SZ_F) && (bx.w - bx.y >= MIN_SZ_F);
        g_score[(size_t)b * A_N + i] = valid ? s : -1.0f;
        if (valid) atomicAdd(&h[bucket_of(s)], 1);
    }
    __syncthreads();
    for (int i = threadIdx.x; i < NB; i += blockDim.x) {
        int v = h[i];
        if (v) atomicAdd(&g_hist[b * NB + i], v);
    }
}

// ---------------- kernel 2: threshold bucket (suffix count >= PRE) -------------
__global__ void k_thr() {                  // grid=BATCH, block=256
    __shared__ int ps[256];
    int b = blockIdx.x, t = threadIdx.x;
    int s = 0;
    int hi = NB - 1 - t * 32;
    for (int j = 0; j < 32; j++) s += g_hist[b * NB + hi - j];
    ps[t] = s;
    __syncthreads();
    if (t == 0) {
        int run = 0, thr = 0;
        for (int c = 0; c < 256; c++) {
            if (run + ps[c] >= PRE) {
                int bb = NB - 1 - c * 32;
                for (int j = 0; j < 32; j++) {
                    run += g_hist[b * NB + bb - j];
                    if (run >= PRE) { thr = bb - j; break; }
                }
                break;
            }
            run += ps[c];
        }
        g_thr[b] = thr;                    // 0 if never reached
    }
}

// ---------------- kernel 3: block-aggregated collect ----------------
__global__ void k_collect() {
    __shared__ int s_cnt, s_base;
    int b = blockIdx.x >> 6;
    int chunk = blockIdx.x & 63;
    const int per = A_N / 64;
    int start = chunk * per;
    int tid = threadIdx.x;
    int thr = g_thr[b];
    if (tid == 0) s_cnt = 0;
    __syncthreads();
    int   li[8];
    float lv[8];
    int c = 0;
    for (int i = start + tid; i < start + per; i += blockDim.x) {
        float s = g_score[(size_t)b * A_N + i];
        if (s >= 0.0f && bucket_of(s) >= thr) { li[c] = i; lv[c] = s; c++; }
    }
    int ofs = 0;
    if (c) ofs = atomicAdd(&s_cnt, c);
    __syncthreads();
    if (tid == 0) s_base = s_cnt ? atomicAdd(&g_cnt[b], s_cnt) : 0;
    __syncthreads();
    int base = s_base + ofs;
    for (int k = 0; k < c; k++) {
        int pos = base + k;
        if (pos < CAP) {
            unsigned lo = ~(unsigned)li[k];            // lower index wins ties
            g_cand[b * CAP + pos] = ((u64)__float_as_uint(lv[k]) << 32) | lo;
        }
    }
}

// ---------------- kernel 4: bitonic sort (desc) + gather ----------------
__device__ __forceinline__ void cex(u64& a, u64& b, bool desc) {
    bool sw = desc ? (a < b) : (a > b);
    if (sw) { u64 t = a; a = b; b = t; }
}

__device__ __forceinline__ void emit(const float4* __restrict__ anchors,
                                     const float4* __restrict__ deltas,
                                     int b, int g, u64 key) {
    if (g >= PRE) return;
    unsigned idx = ~(unsigned)(key & 0xffffffffu);
    float sc;
    float4 bx;
    if (key != 0ull && idx < A_N) {
        sc = __uint_as_float((unsigned)(key >> 32));
        bx = decode_clip(anchors[idx], deltas[(size_t)b * A_N + idx]);
    } else {
        sc = 0.0f;
        bx = make_float4(0.f, 0.f, 0.f, 0.f);
    }
    g_box[b * PRE + g] = bx;
    g_sc2[b * PRE + g] = sc;
}

__global__ void k_sort(const float4* __restrict__ anchors,
                       const float4* __restrict__ deltas) {
    __shared__ u64 sh[CAP];                // 32 KB
    const unsigned FULL = 0xffffffffu;
    int b = blockIdx.x;
    int t = threadIdx.x;                   // 1024 threads
    int C = min(g_cnt[b], CAP);

    if (C <= 2048) {
        // ---- fast path: 2048 keys, 2 per thread ----
        int g0 = t * 2;
        u64 v0 = (g0     < C) ? g_cand[b * CAP + g0]     : 0ull;
        u64 v1 = (g0 + 1 < C) ? g_cand[b * CAP + g0 + 1] : 0ull;
        for (int k = 2; k <= 2048; k <<= 1) {
            for (int j = k >> 1; j > 0; j >>= 1) {
                bool desc = (g0 & k) == 0;
                if (j >= 64) {
                    sh[g0] = v0; sh[g0 + 1] = v1;
                    __syncthreads();
                    bool kmax = (desc == ((g0 & j) == 0));
                    u64 p0 = sh[g0 ^ j], p1 = sh[(g0 + 1) ^ j];
                    v0 = kmax ? (p0 > v0 ? p0 : v0) : (p0 < v0 ? p0 : v0);
                    v1 = kmax ? (p1 > v1 ? p1 : v1) : (p1 < v1 ? p1 : v1);
                    __syncthreads();
                } else if (j >= 2) {
                    int lm = j >> 1;
                    bool kmax = (desc == ((g0 & j) == 0));
                    u64 p0 = __shfl_xor_sync(FULL, v0, lm);
                    u64 p1 = __shfl_xor_sync(FULL, v1, lm);
                    v0 = kmax ? (p0 > v0 ? p0 : v0) : (p0 < v0 ? p0 : v0);
                    v1 = kmax ? (p1 > v1 ? p1 : v1) : (p1 < v1 ? p1 : v1);
                } else {
                    cex(v0, v1, desc);
                }
            }
        }
        emit(anchors, deltas, b, g0, v0);
        emit(anchors, deltas, b, g0 + 1, v1);
    } else {
        // ---- fallback: 4096 keys, 4 per thread ----
        u64 v[4];
        int g0 = t * 4;
        #pragma unroll
        for (int m = 0; m < 4; m++) {
            int g = g0 + m;
            v[m] = (g < C) ? g_cand[b * CAP + g] : 0ull;
        }
        for (int k = 2; k <= CAP; k <<= 1) {
            for (int j = k >> 1; j > 0; j >>= 1) {
                if (j >= 128) {
                    #pragma unroll
                    for (int m = 0; m < 4; m++) sh[g0 + m] = v[m];
                    __syncthreads();
                    bool kmax = (((g0 & k) == 0) == ((g0 & j) == 0));
                    #pragma unroll
                    for (int m = 0; m < 4; m++) {
                        u64 pv = sh[(g0 + m) ^ j];
                        v[m] = kmax ? (pv > v[m] ? pv : v[m]) : (pv < v[m] ? pv : v[m]);
                    }
                    __syncthreads();
                } else if (j >= 4) {
                    int lm = j >> 2;
                    bool kmax = (((g0 & k) == 0) == ((g0 & j) == 0));
                    #pragma unroll
                    for (int m = 0; m < 4; m++) {
                        u64 pv = __shfl_xor_sync(FULL, v[m], lm);
                        v[m] = kmax ? (pv > v[m] ? pv : v[m]) : (pv < v[m] ? pv : v[m]);
                    }
                } else if (j == 2) {
                    bool desc = (g0 & k) == 0;
                    cex(v[0], v[2], desc);
                    cex(v[1], v[3], desc);
                } else {
                    if (k == 2) { cex(v[0], v[1], true); cex(v[2], v[3], false); }
                    else {
                        bool desc = (g0 & k) == 0;
                        cex(v[0], v[1], desc);
                        cex(v[2], v[3], desc);
                    }
                }
            }
        }
        #pragma unroll
        for (int m = 0; m < 4; m++) emit(anchors, deltas, b, g0 + m, v[m]);
    }
}

// ---------------- kernel 5: IoU suppression bitmask (upper triangle only) -------
__global__ void k_iou() {
    __shared__ float4 cb[64];
    __shared__ float  ca[64];
    int rowbase = blockIdx.y * 64;
    int colbase = blockIdx.x * 64;
    if (colbase + 63 <= rowbase) return;   // lower-tri words stay 0 (zero-init)
    int b = blockIdx.z;
    int t = threadIdx.x;
    int j = colbase + t;
    float4 cj = (j < PRE) ? g_box[b * PRE + j] : make_float4(0.f, 0.f, 0.f, 0.f);
    cb[t] = cj;
    ca[t] = (cj.z - cj.x) * (cj.w - cj.y);
    __syncthreads();
    int i = rowbase + t;
    if (i >= PRE) return;
    float4 bi = g_box[b * PRE + i];
    float  ai = (bi.z - bi.x) * (bi.w - bi.y);
    u64 word = 0ull;
    #pragma unroll 8
    for (int jj = 0; jj < 64; jj++) {
        int jg = colbase + jj;
        if (jg > i && jg < PRE) {
            float4 bb = cb[jj];
            float lx = fmaxf(bi.x, bb.x), ly = fmaxf(bi.y, bb.y);
            float rx = fminf(bi.z, bb.z), ry = fminf(bi.w, bb.w);
            float w = fmaxf(rx - lx, 0.0f), h = fmaxf(ry - ly, 0.0f);
            float inter = w * h;
            float iou = inter / (ai + ca[jj] - inter + 1e-6f);
            if (iou > NMS_THR_F) word |= (1ull << jj);
        }
    }
    g_mask[((size_t)b * PRE + i) * NW + blockIdx.x] = word;
}

// ---------------- kernel 6: greedy scan + fused output -------------------------
__global__ void k_nms_out(float* __restrict__ out) {
    __shared__ u64 buf[2][64 * NW];        // 32 KB double buffer
    const int NCH = (PRE + 63) / 64;       // 32 (last chunk: 16 rows)
    const unsigned FULL = 0xffffffffu;
    int b = blockIdx.x;
    int tid = threadIdx.x;
    int warp = tid >> 5;
    int lane = tid & 31;
    const u64* __restrict__ M = &g_mask[(size_t)b * PRE * NW];

    for (int i = tid; i < 64 * NW; i += 1024) buf[0][i] = M[i];
    __syncthreads();

    u64 remv = 0ull;                       // warp0: lane t owns removal word t
    for (int c = 0; c < NCH; c++) {
        if (warp == 0) {
            const u64* dp = buf[c & 1];
            u64 cur = __shfl_sync(FULL, remv, c);
            unsigned keptlo = 0, kepthi = 0;
            u64 newcur = 0ull;
            if (lane == 0) {
                unsigned clo = (unsigned)cur, chi = (unsigned)(cur >> 32);
                #pragma unroll
                for (int r = 0; r < 32; r++) {
                    u64 d = dp[r * NW + c];
                    unsigned sel = ((clo >> r) & 1u) - 1u;   // kept -> ~0
                    clo |= (unsigned)d & sel;
                    chi |= (unsigned)(d >> 32) & sel;
                }
                #pragma unroll
                for (int r = 32; r < 64; r++) {
                    u64 d = dp[r * NW + c];
                    unsigned sel = ((chi >> (r - 32)) & 1u) - 1u;
                    chi |= (unsigned)(d >> 32) & sel;        // low half is 0 here
                }
                keptlo = ~clo; kepthi = ~chi;
                newcur = ((u64)chi << 32) | clo;
            }
            unsigned klo = __shfl_sync(FULL, keptlo, 0);
            unsigned khi = __shfl_sync(FULL, kepthi, 0);
            newcur = __shfl_sync(FULL, newcur, 0);
            if (c == NCH - 1) { klo &= 0xFFFFu; khi = 0u; }  // 16 valid rows
            if (lane == c) remv = newcur;
            #pragma unroll 4
            for (int r = 0; r < 32; r++)
                if ((klo >> r) & 1u) remv |= dp[r * NW + lane];
            #pragma unroll 4
            for (int r = 0; r < 32; r++)
                if ((khi >> r) & 1u) remv |= dp[(r + 32) * NW + lane];
        } else if (c + 1 < NCH) {
            int base = (c + 1) * 64;
            for (int i = tid - 32; i < 64 * NW; i += 992) {
                int r = i >> 5, w = i & 31;
                int row = base + r;
                buf[(c + 1) & 1][i] = (row < PRE) ? M[(size_t)row * NW + w] : 0ull;
            }
        }
        __syncthreads();
    }

    float* ob = &out[(size_t)b * POST * 5];
    for (int i = tid; i < POST * 5; i += 1024) ob[i] = 0.0f;
    __syncthreads();

    if (warp == 0) {
        u64 keepw = ~remv;
        if (lane == NW - 1) keepw &= (1ull << (PRE - (NW - 1) * 64)) - 1ull;
        int pc = __popcll(keepw);
        int inc = pc;
        #pragma unroll
        for (int o = 1; o < 32; o <<= 1) {
            int n = __shfl_up_sync(FULL, inc, o);
            if (lane >= o) inc += n;
        }
        int r = inc - pc;                  // exclusive prefix
        u64 w = keepw;
        while (w) {
            int bit = __ffsll((long long)w) - 1;
            w &= w - 1;
            if (r < POST) {
                int i = lane * 64 + bit;
                float4 bx = g_box[b * PRE + i];
                float sc = g_sc2[b * PRE + i];
                float* o = &ob[(size_t)r * 5];
                o[0] = bx.x; o[1] = bx.y; o[2] = bx.z; o[3] = bx.w; o[4] = sc;
            }
            r++;
        }
    }
}

// ---------------- launch ----------------
extern "C" void kernel_launch(void* const* d_in, const int* in_sizes, int n_in,
                              void* d_out, int out_size) {
    const float4* anchors = (const float4*)d_in[0];   // (A,4)
    const float4* deltas  = (const float4*)d_in[1];   // (B,A,4)
    const float*  scores  = (const float*)d_in[2];    // (B,A)
    float* out = (float*)d_out;                        // (B,POST,5)

    k_zero    <<<(BATCH * NB + 1023) / 1024, 1024>>>();
    k_decode  <<<BATCH * 64, 512>>>(anchors, deltas, scores);
    k_thr     <<<BATCH, 256>>>();
    k_collect <<<BATCH * 64, 512>>>();
    k_sort    <<<BATCH, 1024>>>(anchors, deltas);
    k_iou     <<<dim3(NW, (PRE + 63) / 64, BATCH), 64>>>();
    k_nms_out <<<BATCH, 1024>>>(out);
}

// round 6
// speedup vs baseline: 1.7237x; 1.0781x over previous
#include <cuda_runtime.h>
#include <cstdint>

#define BATCH 16
#define A_N   261888
#define NWRD  8184          // A_N/32 validity words per image
#define PRE   2000
#define POST  1000
#define NB    8192          // histogram buckets over [HLO, 1.0)
#define CAP   8192          // raw candidate storage (prefilter s>=PREF)
#define SORTN 4096          // max sort size
#define NW    32            // 32 x uint64 words cover 2048 >= PRE bits
#define IMGF      1024.0f
#define NMS_THR_F 0.7f
#define MIN_SZ_F  16.0f
#define HLO       0.9f
#define HSCALE    81920.0f  // NB / (1 - HLO)
#define PREF      0.98f
#define THR_SAFE  6560      // bucket above which prefilter 0.98 provably covers

typedef unsigned long long u64;

// ---------------- device scratch ----------------
__device__ unsigned g_valid[BATCH * NWRD];
__device__ int    g_hist[BATCH * NB];
__device__ int    g_thr[BATCH];
__device__ int    g_fb[BATCH];
__device__ int    g_cnt[BATCH];
__device__ u64    g_cand[BATCH * CAP];
__device__ float4 g_box[BATCH * PRE];
__device__ float  g_sc2[BATCH * PRE];
__device__ u64    g_mask[BATCH * PRE * NW];    // lower-tri words never written: stay 0

// ---------------- fast exp: FMA pipe only, ~5e-9 rel err ----------------
__device__ __forceinline__ float fast_exp(float x) {
    x = fmaxf(x, -80.0f);
    float z = fmaf(x, 1.4426950408889634f, 12582912.0f);
    float nf = z - 12582912.0f;
    int   ni = __float_as_int(z) - 0x4B400000;
    float t = fmaf(nf, -0.693145751953125f, x);
    t = fmaf(nf, -1.42860677e-6f, t);
    float p = 1.9841270e-4f;
    p = fmaf(p, t, 1.3888889e-3f);
    p = fmaf(p, t, 8.3333338e-3f);
    p = fmaf(p, t, 4.1666668e-2f);
    p = fmaf(p, t, 1.6666667e-1f);
    p = fmaf(p, t, 5.0e-1f);
    p = fmaf(p, t, 1.0f);
    p = fmaf(p, t, 1.0f);
    return p * __int_as_float((ni + 127) << 23);
}

__device__ __forceinline__ float4 decode_clip(const float4 a, const float4 d) {
    float aw = a.z - a.x;
    float ah = a.w - a.y;
    float ax = a.x + 0.5f * aw;
    float ay = a.y + 0.5f * ah;
    float dw = fminf(d.z, 4.0f);
    float dh = fminf(d.w, 4.0f);
    float px = d.x * aw + ax;
    float py = d.y * ah + ay;
    float pw = fast_exp(dw) * aw;
    float ph = fast_exp(dh) * ah;
    float x1 = fminf(fmaxf(px - 0.5f * pw, 0.0f), IMGF);
    float y1 = fminf(fmaxf(py - 0.5f * ph, 0.0f), IMGF);
    float x2 = fminf(fmaxf(px + 0.5f * pw, 0.0f), IMGF);
    float y2 = fminf(fmaxf(py + 0.5f * ph, 0.0f), IMGF);
    return make_float4(x1, y1, x2, y2);
}

__device__ __forceinline__ int bucket_of(float s) {   // requires s >= HLO
    int bk = (int)((s - HLO) * HSCALE);
    return bk > NB - 1 ? NB - 1 : bk;
}

// ---------------- kernel 0: zero per-launch state ----------------
__global__ void k_zero() {
    int i = blockIdx.x * blockDim.x + threadIdx.x;
    if (i < BATCH * NB) g_hist[i] = 0;
    if (i < BATCH) g_cnt[i] = 0;
}

// ---------------- kernel 1: decode + validity bitmap + range-hist + prefilter collect
__global__ void k_decode(const float4* __restrict__ anchors,
                         const float4* __restrict__ deltas,
                         const float* __restrict__ scores) {
    __shared__ int h[NB];                  // 32 KB
    __shared__ int s_cnt, s_base;
    const unsigned FULL = 0xffffffffu;
    int b = blockIdx.x >> 6;
    int chunk = blockIdx.x & 63;
    int start = chunk * 4096;
    int end = min(start + 4096, A_N);      // last chunk: 3840 (multiple of 32)
    int tid = threadIdx.x;
    for (int i = tid; i < NB; i += blockDim.x) h[i] = 0;
    if (tid == 0) s_cnt = 0;
    __syncthreads();
    int   li[8];
    float lv[8];
    int c = 0;
    for (int i = start + tid; i < end; i += blockDim.x) {
        float4 a = anchors[i];
        float4 d = deltas[(size_t)b * A_N + i];
        float  s = scores[(size_t)b * A_N + i];
        float4 bx = decode_clip(a, d);
        bool valid = (bx.z - bx.x >= MIN_SZ_F) && (bx.w - bx.y >= MIN_SZ_F);
        unsigned m = __ballot_sync(FULL, valid);
        if ((tid & 31) == 0) g_valid[b * NWRD + (i >> 5)] = m;
        if (valid && s >= HLO) atomicAdd(&h[bucket_of(s)], 1);
        if (valid && s >= PREF) { li[c] = i; lv[c] = s; c++; }
    }
    __syncthreads();
    for (int i = tid; i < NB; i += blockDim.x) {
        int v = h[i];
        if (v) atomicAdd(&g_hist[b * NB + i], v);
    }
    int ofs = 0;
    if (c) ofs = atomicAdd(&s_cnt, c);
    __syncthreads();
    if (tid == 0) s_base = s_cnt ? atomicAdd(&g_cnt[b], s_cnt) : 0;
    __syncthreads();
    int base = s_base + ofs;
    for (int k = 0; k < c; k++) {
        int pos = base + k;
        if (pos < CAP) {
            unsigned lo = ~(unsigned)li[k];            // lower index wins ties
            g_cand[b * CAP + pos] = ((u64)__float_as_uint(lv[k]) << 32) | lo;
        }
    }
}

// ---------------- kernel 2: threshold bucket (suffix count >= PRE) -------------
__global__ void k_thr() {                  // grid=BATCH, block=256
    __shared__ int ps[256];
    int b = blockIdx.x, t = threadIdx.x;
    int s = 0;
    int hi = NB - 1 - t * 32;
    for (int j = 0; j < 32; j++) s += g_hist[b * NB + hi - j];
    ps[t] = s;
    __syncthreads();
    if (t == 0) {
        int run = 0, thr = -1;
        for (int c = 0; c < 256; c++) {
            if (run + ps[c] >= PRE) {
                int bb = NB - 1 - c * 32;
                for (int j = 0; j < 32; j++) {
                    run += g_hist[b * NB + bb - j];
                    if (run >= PRE) { thr = bb - j; break; }
                }
                break;
            }
            run += ps[c];
        }
        g_thr[b] = thr;
        g_fb[b] = (thr < 0) ? 2 : ((thr >= THR_SAFE) ? 0 : 1);
    }
}

// ---------------- kernel 3: filter -> bitonic sort (desc) -> gather -------------
__device__ __forceinline__ void cex(u64& a, u64& b, bool desc) {
    bool sw = desc ? (a < b) : (a > b);
    if (sw) { u64 t = a; a = b; b = t; }
}

__device__ __forceinline__ void emit(const float4* __restrict__ anchors,
                                     const float4* __restrict__ deltas,
                                     int b, int g, u64 key) {
    if (g >= PRE) return;
    unsigned idx = ~(unsigned)(key & 0xffffffffu);
    float sc;
    float4 bx;
    if (key != 0ull && idx < A_N) {
        sc = __uint_as_float((unsigned)(key >> 32));
        bx = decode_clip(anchors[idx], deltas[(size_t)b * A_N + idx]);
    } else {
        sc = 0.0f;
        bx = make_float4(0.f, 0.f, 0.f, 0.f);
    }
    g_box[b * PRE + g] = bx;
    g_sc2[b * PRE + g] = sc;
}

__global__ void k_sort(const float4* __restrict__ anchors,
                       const float4* __restrict__ deltas,
                       const float* __restrict__ scores) {
    __shared__ u64 sh[SORTN];              // 32 KB: filtered list, then sort scratch
    __shared__ int s_n;
    const unsigned FULL = 0xffffffffu;
    int b = blockIdx.x;
    int t = threadIdx.x;                   // 1024 threads
    int thr = g_thr[b];
    int fb = g_fb[b];
    int C = g_cnt[b];
    if (fb == 0 && C > CAP) fb = 1;        // prefilter overflowed: rescan
    if (t == 0) s_n = 0;
    __syncthreads();

    if (fb == 0) {
        // filter raw candidates by exact histogram threshold
        int n = min(C, CAP);
        for (int i = t; i < n; i += 1024) {
            u64 key = g_cand[b * CAP + i];
            float s = __uint_as_float((unsigned)(key >> 32));
            if (bucket_of(s) >= thr) {
                int pos = atomicAdd(&s_n, 1);
                if (pos < SORTN) sh[pos] = key;
            }
        }
    } else {
        // cold fallback: rescan all scores with validity bitmap
        for (int i = t; i < A_N; i += 1024) {
            unsigned w = g_valid[b * NWRD + (i >> 5)];
            if ((w >> (i & 31)) & 1u) {
                float s = scores[(size_t)b * A_N + i];
                bool take = (fb == 2) ? true : (s >= HLO && bucket_of(s) >= thr);
                if (take) {
                    int pos = atomicAdd(&s_n, 1);
                    if (pos < SORTN)
                        sh[pos] = ((u64)__float_as_uint(s) << 32) | ~(unsigned)i;
                }
            }
        }
    }
    __syncthreads();
    int n = min(s_n, SORTN);

    if (n <= 2048) {
        // ---- fast path: 2048 keys, 2 per thread ----
        int g0 = t * 2;
        u64 v0 = (g0     < n) ? sh[g0]     : 0ull;
        u64 v1 = (g0 + 1 < n) ? sh[g0 + 1] : 0ull;
        __syncthreads();
        for (int k = 2; k <= 2048; k <<= 1) {
            for (int j = k >> 1; j > 0; j >>= 1) {
                bool desc = (g0 & k) == 0;
                if (j >= 64) {
                    sh[g0] = v0; sh[g0 + 1] = v1;
                    __syncthreads();
                    bool kmax = (desc == ((g0 & j) == 0));
                    u64 p0 = sh[g0 ^ j], p1 = sh[(g0 + 1) ^ j];
                    v0 = kmax ? (p0 > v0 ? p0 : v0) : (p0 < v0 ? p0 : v0);
                    v1 = kmax ? (p1 > v1 ? p1 : v1) : (p1 < v1 ? p1 : v1);
                    __syncthreads();
                } else if (j >= 2) {
                    int lm = j >> 1;
                    bool kmax = (desc == ((g0 & j) == 0));
                    u64 p0 = __shfl_xor_sync(FULL, v0, lm);
                    u64 p1 = __shfl_xor_sync(FULL, v1, lm);
                    v0 = kmax ? (p0 > v0 ? p0 : v0) : (p0 < v0 ? p0 : v0);
                    v1 = kmax ? (p1 > v1 ? p1 : v1) : (p1 < v1 ? p1 : v1);
                } else {
                    cex(v0, v1, desc);
                }
            }
        }
        emit(anchors, deltas, b, g0, v0);
        emit(anchors, deltas, b, g0 + 1, v1);
    } else {
        // ---- fallback: 4096 keys, 4 per thread ----
        u64 v[4];
        int g0 = t * 4;
        #pragma unroll
        for (int m = 0; m < 4; m++) {
            int g = g0 + m;
            v[m] = (g < n) ? sh[g] : 0ull;
        }
        __syncthreads();
        for (int k = 2; k <= SORTN; k <<= 1) {
            for (int j = k >> 1; j > 0; j >>= 1) {
                if (j >= 128) {
                    #pragma unroll
                    for (int m = 0; m < 4; m++) sh[g0 + m] = v[m];
                    __syncthreads();
                    bool kmax = (((g0 & k) == 0) == ((g0 & j) == 0));
                    #pragma unroll
                    for (int m = 0; m < 4; m++) {
                        u64 pv = sh[(g0 + m) ^ j];
                        v[m] = kmax ? (pv > v[m] ? pv : v[m]) : (pv < v[m] ? pv : v[m]);
                    }
                    __syncthreads();
                } else if (j >= 4) {
                    int lm = j >> 2;
                    bool kmax = (((g0 & k) == 0) == ((g0 & j) == 0));
                    #pragma unroll
                    for (int m = 0; m < 4; m++) {
                        u64 pv = __shfl_xor_sync(FULL, v[m], lm);
                        v[m] = kmax ? (pv > v[m] ? pv : v[m]) : (pv < v[m] ? pv : v[m]);
                    }
                } else if (j == 2) {
                    bool desc = (g0 & k) == 0;
                    cex(v[0], v[2], desc);
                    cex(v[1], v[3], desc);
                } else {
                    if (k == 2) { cex(v[0], v[1], true); cex(v[2], v[3], false); }
                    else {
                        bool desc = (g0 & k) == 0;
                        cex(v[0], v[1], desc);
                        cex(v[2], v[3], desc);
                    }
                }
            }
        }
        #pragma unroll
        for (int m = 0; m < 4; m++) emit(anchors, deltas, b, g0 + m, v[m]);
    }
}

// ---------------- kernel 4: IoU suppression bitmask (upper triangle only) -------
__global__ void k_iou() {
    __shared__ float4 cb[64];
    __shared__ float  ca[64];
    int rowbase = blockIdx.y * 64;
    int colbase = blockIdx.x * 64;
    if (colbase + 63 <= rowbase) return;   // lower-tri words stay 0
    int b = blockIdx.z;
    int t = threadIdx.x;
    int j = colbase + t;
    float4 cj = (j < PRE) ? g_box[b * PRE + j] : make_float4(0.f, 0.f, 0.f, 0.f);
    cb[t] = cj;
    ca[t] = (cj.z - cj.x) * (cj.w - cj.y);
    __syncthreads();
    int i = rowbase + t;
    if (i >= PRE) return;
    float4 bi = g_box[b * PRE + i];
    float  ai = (bi.z - bi.x) * (bi.w - bi.y);
    u64 word = 0ull;
    #pragma unroll 8
    for (int jj = 0; jj < 64; jj++) {
        int jg = colbase + jj;
        if (jg > i && jg < PRE) {
            float4 bb = cb[jj];
            float lx = fmaxf(bi.x, bb.x), ly = fmaxf(bi.y, bb.y);
            float rx = fminf(bi.z, bb.z), ry = fminf(bi.w, bb.w);
            float w = fmaxf(rx - lx, 0.0f), h = fmaxf(ry - ly, 0.0f);
            float inter = w * h;
            float iou = inter / (ai + ca[jj] - inter + 1e-6f);
            if (iou > NMS_THR_F) word |= (1ull << jj);
        }
    }
    g_mask[((size_t)b * PRE + i) * NW + blockIdx.x] = word;
}

// ---------------- kernel 5: greedy scan + fused output -------------------------
__global__ void k_nms_out(float* __restrict__ out) {
    __shared__ u64 buf[2][64 * NW];        // 32 KB double buffer
    const int NCH = (PRE + 63) / 64;       // 32 (last chunk: 16 rows)
    const unsigned FULL = 0xffffffffu;
    int b = blockIdx.x;
    int tid = threadIdx.x;
    int warp = tid >> 5;
    int lane = tid & 31;
    const u64* __restrict__ M = &g_mask[(size_t)b * PRE * NW];

    for (int i = tid; i < 64 * NW; i += 1024) buf[0][i] = M[i];
    __syncthreads();

    u64 remv = 0ull;                       // warp0: lane t owns removal word t
    for (int c = 0; c < NCH; c++) {
        if (warp == 0) {
            const u64* dp = buf[c & 1];
            u64 cur = __shfl_sync(FULL, remv, c);
            unsigned keptlo = 0, kepthi = 0;
            u64 newcur = 0ull;
            if (lane == 0) {
                unsigned clo = (unsigned)cur, chi = (unsigned)(cur >> 32);
                #pragma unroll
                for (int r = 0; r < 32; r++) {
                    u64 d = dp[r * NW + c];
                    unsigned sel = ((clo >> r) & 1u) - 1u;   // kept -> ~0
                    clo |= (unsigned)d & sel;
                    chi |= (unsigned)(d >> 32) & sel;
                }
                #pragma unroll
                for (int r = 32; r < 64; r++) {
                    u64 d = dp[r * NW + c];
                    unsigned sel = ((chi >> (r - 32)) & 1u) - 1u;
                    chi |= (unsigned)(d >> 32) & sel;        // low half is 0 here
                }
                keptlo = ~clo; kepthi = ~chi;
                newcur = ((u64)chi << 32) | clo;
            }
            unsigned klo = __shfl_sync(FULL, keptlo, 0);
            unsigned khi = __shfl_sync(FULL, kepthi, 0);
            newcur = __shfl_sync(FULL, newcur, 0);
            if (c == NCH - 1) { klo &= 0xFFFFu; khi = 0u; }  // 16 valid rows
            if (lane == c) remv = newcur;
            #pragma unroll 4
            for (int r = 0; r < 32; r++)
                if ((klo >> r) & 1u) remv |= dp[r * NW + lane];
            #pragma unroll 4
            for (int r = 0; r < 32; r++)
                if ((khi >> r) & 1u) remv |= dp[(r + 32) * NW + lane];
        } else if (c + 1 < NCH) {
            int base = (c + 1) * 64;
            for (int i = tid - 32; i < 64 * NW; i += 992) {
                int r = i >> 5, w = i & 31;
                int row = base + r;
                buf[(c + 1) & 1][i] = (row < PRE) ? M[(size_t)row * NW + w] : 0ull;
            }
        }
        __syncthreads();
    }

    float* ob = &out[(size_t)b * POST * 5];
    for (int i = tid; i < POST * 5; i += 1024) ob[i] = 0.0f;
    __syncthreads();

    if (warp == 0) {
        u64 keepw = ~remv;
        if (lane == NW - 1) keepw &= (1ull << (PRE - (NW - 1) * 64)) - 1ull;
        int pc = __popcll(keepw);
        int inc = pc;
        #pragma unroll
        for (int o = 1; o < 32; o <<= 1) {
            int nn = __shfl_up_sync(FULL, inc, o);
            if (lane >= o) inc += nn;
        }
        int r = inc - pc;                  // exclusive prefix
        u64 w = keepw;
        while (w) {
            int bit = __ffsll((long long)w) - 1;
            w &= w - 1;
            if (r < POST) {
                int i = lane * 64 + bit;
                float4 bx = g_box[b * PRE + i];
                float sc = g_sc2[b * PRE + i];
                float* o = &ob[(size_t)r * 5];
                o[0] = bx.x; o[1] = bx.y; o[2] = bx.z; o[3] = bx.w; o[4] = sc;
            }
            r++;
        }
    }
}

// ---------------- launch ----------------
extern "C" void kernel_launch(void* const* d_in, const int* in_sizes, int n_in,
                              void* d_out, int out_size) {
    const float4* anchors = (const float4*)d_in[0];   // (A,4)
    const float4* deltas  = (const float4*)d_in[1];   // (B,A,4)
    const float*  scores  = (const float*)d_in[2];    // (B,A)
    float* out = (float*)d_out;                        // (B,POST,5)

    k_zero    <<<(BATCH * NB + 1023) / 1024, 1024>>>();
    k_decode  <<<BATCH * 64, 512>>>(anchors, deltas, scores);
    k_thr     <<<BATCH, 256>>>();
    k_sort    <<<BATCH, 1024>>>(anchors, deltas, scores);
    k_iou     <<<dim3(NW, (PRE + 63) / 64, BATCH), 64>>>();
    k_nms_out <<<BATCH, 1024>>>(out);
}

// round 7
// speedup vs baseline: 1.7987x; 1.0435x over previous
#include <cuda_runtime.h>
#include <cstdint>

#define BATCH 16
#define A_N   261888
#define NWRD  8184          // A_N/32 validity words per image
#define PRE   2000
#define POST  1000
#define SORTN 4096          // max sort size
#define NSEG  64            // chunks per image
#define SEGSZ 256           // candidate slots per chunk
#define NCAND (NSEG * SEGSZ)
#define NH    2048          // selection histogram buckets over [PREF, 1)
#define NW    32            // 32 x uint64 words cover 2048 >= PRE bits
#define IMGF      1024.0f
#define NMS_THR_F 0.7f
#define MIN_SZ_F  16.0f
#define PREF      0.98f
#define HSCALE    102400.0f // NH / (1 - PREF)

typedef unsigned long long u64;

// ---------------- device scratch ----------------
__device__ unsigned g_valid[BATCH * NWRD];
__device__ int    g_ccnt[BATCH * NSEG];        // written unconditionally each launch
__device__ u64    g_cand[BATCH * NCAND];
__device__ float4 g_box[BATCH * PRE];
__device__ float  g_sc2[BATCH * PRE];
__device__ u64    g_mask[BATCH * PRE * NW];    // lower-tri words never written: stay 0

// ---------------- fast exp: FMA pipe only, ~5e-9 rel err ----------------
__device__ __forceinline__ float fast_exp(float x) {
    x = fmaxf(x, -80.0f);
    float z = fmaf(x, 1.4426950408889634f, 12582912.0f);
    float nf = z - 12582912.0f;
    int   ni = __float_as_int(z) - 0x4B400000;
    float t = fmaf(nf, -0.693145751953125f, x);
    t = fmaf(nf, -1.42860677e-6f, t);
    float p = 1.9841270e-4f;
    p = fmaf(p, t, 1.3888889e-3f);
    p = fmaf(p, t, 8.3333338e-3f);
    p = fmaf(p, t, 4.1666668e-2f);
    p = fmaf(p, t, 1.6666667e-1f);
    p = fmaf(p, t, 5.0e-1f);
    p = fmaf(p, t, 1.0f);
    p = fmaf(p, t, 1.0f);
    return p * __int_as_float((ni + 127) << 23);
}

__device__ __forceinline__ float4 decode_clip(const float4 a, const float4 d) {
    float aw = a.z - a.x;
    float ah = a.w - a.y;
    float ax = a.x + 0.5f * aw;
    float ay = a.y + 0.5f * ah;
    float dw = fminf(d.z, 4.0f);
    float dh = fminf(d.w, 4.0f);
    float px = d.x * aw + ax;
    float py = d.y * ah + ay;
    float pw = fast_exp(dw) * aw;
    float ph = fast_exp(dh) * ah;
    float x1 = fminf(fmaxf(px - 0.5f * pw, 0.0f), IMGF);
    float y1 = fminf(fmaxf(py - 0.5f * ph, 0.0f), IMGF);
    float x2 = fminf(fmaxf(px + 0.5f * pw, 0.0f), IMGF);
    float y2 = fminf(fmaxf(py + 0.5f * ph, 0.0f), IMGF);
    return make_float4(x1, y1, x2, y2);
}

// ---------------- kernel 1: decode + validity bitmap + prefilter collect --------
__global__ void k_decode(const float4* __restrict__ anchors,
                         const float4* __restrict__ deltas,
                         const float* __restrict__ scores) {
    __shared__ int s_cnt;
    const unsigned FULL = 0xffffffffu;
    int b = blockIdx.x >> 6;
    int chunk = blockIdx.x & 63;
    int start = chunk * 4096;
    int end = min(start + 4096, A_N);      // last chunk: 3840 (multiple of 32)
    int tid = threadIdx.x;
    if (tid == 0) s_cnt = 0;
    __syncthreads();
    int   li[8];
    float lv[8];
    int c = 0;
    for (int i = start + tid; i < end; i += blockDim.x) {
        float4 a = anchors[i];
        float4 d = deltas[(size_t)b * A_N + i];
        float  s = scores[(size_t)b * A_N + i];
        float4 bx = decode_clip(a, d);
        bool valid = (bx.z - bx.x >= MIN_SZ_F) && (bx.w - bx.y >= MIN_SZ_F);
        unsigned m = __ballot_sync(FULL, valid);
        if ((tid & 31) == 0) g_valid[b * NWRD + (i >> 5)] = m;
        if (valid && s >= PREF && c < 8) { li[c] = i; lv[c] = s; c++; }
    }
    int ofs = 0;
    if (c) ofs = atomicAdd(&s_cnt, c);     // shared atomic only
    for (int k = 0; k < c; k++) {
        int pos = ofs + k;
        if (pos < SEGSZ) {
            unsigned lo = ~(unsigned)li[k];            // lower index wins ties
            g_cand[(size_t)(b * NSEG + chunk) * SEGSZ + pos] =
                ((u64)__float_as_uint(lv[k]) << 32) | lo;
        }
    }
    __syncthreads();
    if (tid == 0) g_ccnt[b * NSEG + chunk] = s_cnt;    // raw count, every launch
}

// ---------------- kernel 2: select top-PRE + bitonic sort (desc) + gather -------
__device__ __forceinline__ void cex(u64& a, u64& b, bool desc) {
    bool sw = desc ? (a < b) : (a > b);
    if (sw) { u64 t = a; a = b; b = t; }
}

__device__ __forceinline__ void emit(const float4* __restrict__ anchors,
                                     const float4* __restrict__ deltas,
                                     int b, int g, u64 key) {
    if (g >= PRE) return;
    unsigned idx = ~(unsigned)(key & 0xffffffffu);
    float sc;
    float4 bx;
    if (key != 0ull && idx < A_N) {
        sc = __uint_as_float((unsigned)(key >> 32));
        bx = decode_clip(anchors[idx], deltas[(size_t)b * A_N + idx]);
    } else {
        sc = 0.0f;
        bx = make_float4(0.f, 0.f, 0.f, 0.f);
    }
    g_box[b * PRE + g] = bx;
    g_sc2[b * PRE + g] = sc;
}

__global__ void k_sort(const float4* __restrict__ anchors,
                       const float4* __restrict__ deltas,
                       const float* __restrict__ scores) {
    __shared__ u64 sh[SORTN];              // 32 KB: filtered list + sort scratch
    __shared__ int hist[NH];               // 8 KB
    __shared__ int ss[256];
    __shared__ int segc[NSEG];
    __shared__ int s_m, s_thr, s_fb;
    const unsigned FULL = 0xffffffffu;
    int b = blockIdx.x;
    int t = threadIdx.x;                   // 1024 threads

    for (int i = t; i < NH; i += 1024) hist[i] = 0;
    if (t < NSEG) segc[t] = g_ccnt[b * NSEG + t];
    if (t == 0) { s_m = 0; s_fb = 0; }
    __syncthreads();
    if (t == 0) {
        int tot = 0, ov = 0;
        for (int s = 0; s < NSEG; s++) { tot += min(segc[s], SEGSZ); ov |= (segc[s] > SEGSZ); }
        s_fb = (ov || tot < PRE) ? 1 : 0;
    }
    __syncthreads();

    if (!s_fb) {
        // -------- normal path: candidates all have s >= PREF --------
        // pass 1: histogram
        for (int slot = t; slot < NCAND; slot += 1024) {
            int seg = slot >> 8, k = slot & (SEGSZ - 1);
            if (k < min(segc[seg], SEGSZ)) {
                u64 key = g_cand[(size_t)(b * NSEG + seg) * SEGSZ + k];
                float s = __uint_as_float((unsigned)(key >> 32));
                int bk = min((int)((s - PREF) * HSCALE), NH - 1);
                atomicAdd(&hist[bk], 1);
            }
        }
        __syncthreads();
        // threshold: suffix count >= PRE
        if (t < 256) {
            int acc = 0, base = NH - 1 - t * 8;
            for (int j = 0; j < 8; j++) acc += hist[base - j];
            ss[t] = acc;
        }
        __syncthreads();
        if (t == 0) {
            int run = 0, thr = 0;
            for (int c = 0; c < 256; c++) {
                if (run + ss[c] >= PRE) {
                    int base = NH - 1 - c * 8;
                    for (int j = 0; j < 8; j++) {
                        run += hist[base - j];
                        if (run >= PRE) { thr = base - j; break; }
                    }
                    break;
                }
                run += ss[c];
            }
            s_thr = thr;
        }
        __syncthreads();
        int thr = s_thr;
        // pass 2: filter + gather
        for (int slot = t; slot < NCAND; slot += 1024) {
            int seg = slot >> 8, k = slot & (SEGSZ - 1);
            if (k < min(segc[seg], SEGSZ)) {
                u64 key = g_cand[(size_t)(b * NSEG + seg) * SEGSZ + k];
                float s = __uint_as_float((unsigned)(key >> 32));
                int bk = min((int)((s - PREF) * HSCALE), NH - 1);
                if (bk >= thr) {
                    int pos = atomicAdd(&s_m, 1);
                    if (pos < SORTN) sh[pos] = key;
                }
            }
        }
    } else {
        // -------- cold fallback: rescan all scores (256-bucket hist over [0,1))
        for (int i = t; i < A_N; i += 1024) {
            unsigned w = g_valid[b * NWRD + (i >> 5)];
            if ((w >> (i & 31)) & 1u) {
                float s = scores[(size_t)b * A_N + i];
                int bk = min(max((int)(s * 256.0f), 0), 255);
                atomicAdd(&hist[bk], 1);
            }
        }
        __syncthreads();
        if (t == 0) {
            int run = 0, thr = 0;
            for (int k = 255; k >= 0; k--) {
                run += hist[k];
                if (run >= PRE) { thr = k; break; }
            }
            s_thr = thr;
        }
        __syncthreads();
        int thr = s_thr;
        for (int i = t; i < A_N; i += 1024) {
            unsigned w = g_valid[b * NWRD + (i >> 5)];
            if ((w >> (i & 31)) & 1u) {
                float s = scores[(size_t)b * A_N + i];
                int bk = min(max((int)(s * 256.0f), 0), 255);
                if (bk >= thr) {
                    int pos = atomicAdd(&s_m, 1);
                    if (pos < SORTN)
                        sh[pos] = ((u64)__float_as_uint(s) << 32) | ~(unsigned)i;
                }
            }
        }
    }
    __syncthreads();
    int n = min(s_m, SORTN);

    if (n <= 2048) {
        // ---- fast path: 2048 keys, 2 per thread ----
        int g0 = t * 2;
        u64 v0 = (g0     < n) ? sh[g0]     : 0ull;
        u64 v1 = (g0 + 1 < n) ? sh[g0 + 1] : 0ull;
        __syncthreads();
        for (int k = 2; k <= 2048; k <<= 1) {
            for (int j = k >> 1; j > 0; j >>= 1) {
                bool desc = (g0 & k) == 0;
                if (j >= 64) {
                    sh[g0] = v0; sh[g0 + 1] = v1;
                    __syncthreads();
                    bool kmax = (desc == ((g0 & j) == 0));
                    u64 p0 = sh[g0 ^ j], p1 = sh[(g0 + 1) ^ j];
                    v0 = kmax ? (p0 > v0 ? p0 : v0) : (p0 < v0 ? p0 : v0);
                    v1 = kmax ? (p1 > v1 ? p1 : v1) : (p1 < v1 ? p1 : v1);
                    __syncthreads();
                } else if (j >= 2) {
                    int lm = j >> 1;
                    bool kmax = (desc == ((g0 & j) == 0));
                    u64 p0 = __shfl_xor_sync(FULL, v0, lm);
                    u64 p1 = __shfl_xor_sync(FULL, v1, lm);
                    v0 = kmax ? (p0 > v0 ? p0 : v0) : (p0 < v0 ? p0 : v0);
                    v1 = kmax ? (p1 > v1 ? p1 : v1) : (p1 < v1 ? p1 : v1);
                } else {
                    cex(v0, v1, desc);
                }
            }
        }
        emit(anchors, deltas, b, g0, v0);
        emit(anchors, deltas, b, g0 + 1, v1);
    } else {
        // ---- 4096 keys, 4 per thread ----
        u64 v[4];
        int g0 = t * 4;
        #pragma unroll
        for (int m = 0; m < 4; m++) {
            int g = g0 + m;
            v[m] = (g < n) ? sh[g] : 0ull;
        }
        __syncthreads();
        for (int k = 2; k <= SORTN; k <<= 1) {
            for (int j = k >> 1; j > 0; j >>= 1) {
                if (j >= 128) {
                    #pragma unroll
                    for (int m = 0; m < 4; m++) sh[g0 + m] = v[m];
                    __syncthreads();
                    bool kmax = (((g0 & k) == 0) == ((g0 & j) == 0));
                    #pragma unroll
                    for (int m = 0; m < 4; m++) {
                        u64 pv = sh[(g0 + m) ^ j];
                        v[m] = kmax ? (pv > v[m] ? pv : v[m]) : (pv < v[m] ? pv : v[m]);
                    }
                    __syncthreads();
                } else if (j >= 4) {
                    int lm = j >> 2;
                    bool kmax = (((g0 & k) == 0) == ((g0 & j) == 0));
                    #pragma unroll
                    for (int m = 0; m < 4; m++) {
                        u64 pv = __shfl_xor_sync(FULL, v[m], lm);
                        v[m] = kmax ? (pv > v[m] ? pv : v[m]) : (pv < v[m] ? pv : v[m]);
                    }
                } else if (j == 2) {
                    bool desc = (g0 & k) == 0;
                    cex(v[0], v[2], desc);
                    cex(v[1], v[3], desc);
                } else {
                    if (k == 2) { cex(v[0], v[1], true); cex(v[2], v[3], false); }
                    else {
                        bool desc = (g0 & k) == 0;
                        cex(v[0], v[1], desc);
                        cex(v[2], v[3], desc);
                    }
                }
            }
        }
        #pragma unroll
        for (int m = 0; m < 4; m++) emit(anchors, deltas, b, g0 + m, v[m]);
    }
}

// ---------------- kernel 3: IoU suppression bitmask (upper triangle only) -------
__global__ void k_iou() {
    __shared__ float4 cb[64];
    __shared__ float  ca[64];
    int rowbase = blockIdx.y * 64;
    int colbase = blockIdx.x * 64;
    if (colbase + 63 <= rowbase) return;   // lower-tri words stay 0
    int b = blockIdx.z;
    int t = threadIdx.x;
    int j = colbase + t;
    float4 cj = (j < PRE) ? g_box[b * PRE + j] : make_float4(0.f, 0.f, 0.f, 0.f);
    cb[t] = cj;
    ca[t] = (cj.z - cj.x) * (cj.w - cj.y);
    __syncthreads();
    int i = rowbase + t;
    if (i >= PRE) return;
    float4 bi = g_box[b * PRE + i];
    float  ai = (bi.z - bi.x) * (bi.w - bi.y);
    u64 word = 0ull;
    #pragma unroll 8
    for (int jj = 0; jj < 64; jj++) {
        int jg = colbase + jj;
        if (jg > i && jg < PRE) {
            float4 bb = cb[jj];
            float lx = fmaxf(bi.x, bb.x), ly = fmaxf(bi.y, bb.y);
            float rx = fminf(bi.z, bb.z), ry = fminf(bi.w, bb.w);
            float w = fmaxf(rx - lx, 0.0f), h = fmaxf(ry - ly, 0.0f);
            float inter = w * h;
            float iou = inter / (ai + ca[jj] - inter + 1e-6f);
            if (iou > NMS_THR_F) word |= (1ull << jj);
        }
    }
    g_mask[((size_t)b * PRE + i) * NW + blockIdx.x] = word;
}

// ---------------- kernel 4: greedy scan + fused output -------------------------
__global__ void k_nms_out(float* __restrict__ out) {
    __shared__ u64 buf[2][64 * NW];        // 32 KB double buffer
    const int NCH = (PRE + 63) / 64;       // 32 (last chunk: 16 rows)
    const unsigned FULL = 0xffffffffu;
    int b = blockIdx.x;
    int tid = threadIdx.x;
    int warp = tid >> 5;
    int lane = tid & 31;
    const u64* __restrict__ M = &g_mask[(size_t)b * PRE * NW];

    for (int i = tid; i < 64 * NW; i += 1024) buf[0][i] = M[i];
    __syncthreads();

    u64 remv = 0ull;                       // warp0: lane t owns removal word t
    for (int c = 0; c < NCH; c++) {
        if (warp == 0) {
            const u64* dp = buf[c & 1];
            u64 cur = __shfl_sync(FULL, remv, c);
            unsigned keptlo = 0, kepthi = 0;
            u64 newcur = 0ull;
            if (lane == 0) {
                unsigned clo = (unsigned)cur, chi = (unsigned)(cur >> 32);
                #pragma unroll
                for (int r = 0; r < 32; r++) {
                    u64 d = dp[r * NW + c];
                    unsigned sel = ((clo >> r) & 1u) - 1u;   // kept -> ~0
                    clo |= (unsigned)d & sel;
                    chi |= (unsigned)(d >> 32) & sel;
                }
                #pragma unroll
                for (int r = 32; r < 64; r++) {
                    u64 d = dp[r * NW + c];
                    unsigned sel = ((chi >> (r - 32)) & 1u) - 1u;
                    chi |= (unsigned)(d >> 32) & sel;        // low half is 0 here
                }
                keptlo = ~clo; kepthi = ~chi;
                newcur = ((u64)chi << 32) | clo;
            }
            unsigned klo = __shfl_sync(FULL, keptlo, 0);
            unsigned khi = __shfl_sync(FULL, kepthi, 0);
            newcur = __shfl_sync(FULL, newcur, 0);
            if (c == NCH - 1) { klo &= 0xFFFFu; khi = 0u; }  // 16 valid rows
            if (lane == c) remv = newcur;
            #pragma unroll 4
            for (int r = 0; r < 32; r++)
                if ((klo >> r) & 1u) remv |= dp[r * NW + lane];
            #pragma unroll 4
            for (int r = 0; r < 32; r++)
                if ((khi >> r) & 1u) remv |= dp[(r + 32) * NW + lane];
        } else if (c + 1 < NCH) {
            int base = (c + 1) * 64;
            for (int i = tid - 32; i < 64 * NW; i += 992) {
                int r = i >> 5, w = i & 31;
                int row = base + r;
                buf[(c + 1) & 1][i] = (row < PRE) ? M[(size_t)row * NW + w] : 0ull;
            }
        }
        __syncthreads();
    }

    float* ob = &out[(size_t)b * POST * 5];
    for (int i = tid; i < POST * 5; i += 1024) ob[i] = 0.0f;
    __syncthreads();

    if (warp == 0) {
        u64 keepw = ~remv;
        if (lane == NW - 1) keepw &= (1ull << (PRE - (NW - 1) * 64)) - 1ull;
        int pc = __popcll(keepw);
        int inc = pc;
        #pragma unroll
        for (int o = 1; o < 32; o <<= 1) {
            int nn = __shfl_up_sync(FULL, inc, o);
            if (lane >= o) inc += nn;
        }
        int r = inc - pc;                  // exclusive prefix
        u64 w = keepw;
        while (w) {
            int bit = __ffsll((long long)w) - 1;
            w &= w - 1;
            if (r < POST) {
                int i = lane * 64 + bit;
                float4 bx = g_box[b * PRE + i];
                float sc = g_sc2[b * PRE + i];
                float* o = &ob[(size_t)r * 5];
                o[0] = bx.x; o[1] = bx.y; o[2] = bx.z; o[3] = bx.w; o[4] = sc;
            }
            r++;
        }
    }
}

// ---------------- launch ----------------
extern "C" void kernel_launch(void* const* d_in, const int* in_sizes, int n_in,
                              void* d_out, int out_size) {
    const float4* anchors = (const float4*)d_in[0];   // (A,4)
    const float4* deltas  = (const float4*)d_in[1];   // (B,A,4)
    const float*  scores  = (const float*)d_in[2];    // (B,A)
    float* out = (float*)d_out;                        // (B,POST,5)

    k_decode  <<<BATCH * 64, 512>>>(anchors, deltas, scores);
    k_sort    <<<BATCH, 1024>>>(anchors, deltas, scores);
    k_iou     <<<dim3(NW, (PRE + 63) / 64, BATCH), 64>>>();
    k_nms_out <<<BATCH, 1024>>>(out);
}